// round 8
// baseline (speedup 1.0000x reference)
#include <cuda_runtime.h>
#include <math.h>
#include <stdint.h>

#ifndef M_PI
#define M_PI 3.14159265358979323846
#endif

// Intermediate yr, shape [4][340][256][256] fp32 (~357 MB), device global.
__device__ float g_yr[89128960];
// 1 if quant is all-ones (DCT->quant->IDCT is identity), else 0.
__device__ int g_ones;

typedef unsigned long long ull;

// ---- packed f32x2 helpers ----
__device__ __forceinline__ ull pk(float x, float y) {
    ull r;
    asm("mov.b64 %0, {%1, %2};" : "=l"(r) : "r"(__float_as_int(x)), "r"(__float_as_int(y)));
    return r;
}
__device__ __forceinline__ void fma2(ull& d, ull a, ull b) {
    asm("fma.rn.f32x2 %0, %1, %2, %0;" : "+l"(d) : "l"(a), "l"(b));
}
__device__ __forceinline__ float2 upk(ull v) {
    int lo, hi;
    asm("mov.b64 {%0, %1}, %2;" : "=r"(lo), "=r"(hi) : "l"(v));
    return make_float2(__int_as_float(lo), __int_as_float(hi));
}

// ---- cp.async helpers ----
__device__ __forceinline__ void cp4(uint32_t dst, uint64_t gsrc, unsigned sz) {
    asm volatile("cp.async.ca.shared.global [%0], [%1], 4, %2;"
                 :: "r"(dst), "l"(gsrc), "r"(sz));
}
__device__ __forceinline__ void cp_commit() {
    asm volatile("cp.async.commit_group;" ::: "memory");
}
__device__ __forceinline__ void cp_wait1() {
    asm volatile("cp.async.wait_group 1;" ::: "memory");
}
__device__ __forceinline__ uint32_t smem_u32(const void* p) {
    uint32_t a;
    asm("{ .reg .u64 t; cvta.to.shared.u64 t, %1; cvt.u32.u64 %0, t; }"
        : "=r"(a) : "l"(p));
    return a;
}
__device__ __forceinline__ uint64_t gmem_u64(const void* p) {
    uint64_t a;
    asm("cvta.to.global.u64 %0, %1;" : "=l"(a) : "l"(p));
    return a;
}

// ---------------------------------------------------------------------------
// Flag kernels: detect quant == all-ones.
// ---------------------------------------------------------------------------
__global__ void kinit() {
    if (threadIdx.x == 0) g_ones = 1;
}
__global__ void kcheck(const float* __restrict__ quant) {
    int i = blockIdx.x * 256 + threadIdx.x;   // 85*256 == 21760
    if (quant[i] != 1.0f) atomicExch(&g_ones, 0);
}

// ---------------------------------------------------------------------------
// Fast path kernel A2 (quant == ones): proj_in register-blocked f32x2 GEMM.
// CTA = 4x64 pixel tile, 256 threads; 5 guard-free chunks of 64 outputs +
// one 20-output tail chunk (warps with no valid outputs skip entirely).
// Dyn smem: xs[64][256] (64KB) + Wk[64][64] (16KB) = 81920 B.
// ---------------------------------------------------------------------------
__global__ void __launch_bounds__(256, 2) kernA2(
    const float* __restrict__ x, const float* __restrict__ Win)
{
    if (!*(volatile int*)&g_ones) return;

    extern __shared__ float sm[];
    float* xs = sm;            // [c][p]
    float* Wk = sm + 16384;    // [c][o] transposed chunk

    const int t = threadIdx.x;
    const int b = blockIdx.z;
    const int row0 = blockIdx.y * 4;
    const int col0 = blockIdx.x * 64;

    // Stage x tile: 64 ch x 256 px, vectorized float4.
    {
        const float* xb = x + ((size_t)b << 22);
        #pragma unroll
        for (int k = 0; k < 16; k++) {
            int i = t + k * 256;
            int c = i >> 6, q = i & 63;
            int r = q >> 4, cc = (q & 15) * 4;
            float4 v = *(const float4*)(xb + ((size_t)c * 256 + row0 + r) * 256 + col0 + cc);
            *(float4*)(xs + c * 256 + q * 4) = v;
        }
    }

    const int po = t & 31;
    const int oo = t >> 5;
    const int rA = po >> 4, cA = (po * 4) & 63;

    // ---- 5 full chunks, no guards (o0+63 <= 319 < 340) ----
    for (int o0 = 0; o0 < 320; o0 += 64) {
        __syncthreads();
        #pragma unroll
        for (int k = 0; k < 16; k++) {
            int i = t + k * 256;
            int c = i >> 6, o = i & 63;
            Wk[i] = Win[(o0 + o) * 64 + c];
        }
        __syncthreads();

        ull acc[8][4];
        #pragma unroll
        for (int o = 0; o < 8; o++)
            #pragma unroll
            for (int j = 0; j < 4; j++) acc[o][j] = 0ull;

        #pragma unroll 4
        for (int c = 0; c < 64; c++) {
            float4 xa  = *(const float4*)(xs + c * 256 + po * 4);
            float4 xb4 = *(const float4*)(xs + c * 256 + po * 4 + 128);
            ull x0 = pk(xa.x, xa.y),   x1 = pk(xa.z, xa.w);
            ull x2 = pk(xb4.x, xb4.y), x3 = pk(xb4.z, xb4.w);
            float4 wa = *(const float4*)(Wk + c * 64 + oo * 8);
            float4 wb = *(const float4*)(Wk + c * 64 + oo * 8 + 4);
            float wv[8] = {wa.x, wa.y, wa.z, wa.w, wb.x, wb.y, wb.z, wb.w};
            #pragma unroll
            for (int o = 0; o < 8; o++) {
                ull wd = pk(wv[o], wv[o]);
                fma2(acc[o][0], wd, x0);
                fma2(acc[o][1], wd, x1);
                fma2(acc[o][2], wd, x2);
                fma2(acc[o][3], wd, x3);
            }
        }

        #pragma unroll
        for (int o = 0; o < 8; o++) {
            int og = o0 + oo * 8 + o;
            float2 p0 = upk(acc[o][0]), p1 = upk(acc[o][1]);
            float2 p2 = upk(acc[o][2]), p3 = upk(acc[o][3]);
            size_t pl = ((size_t)b * 340 + og) * 65536;
            *(float4*)(g_yr + pl + (size_t)(row0 + rA) * 256 + col0 + cA) =
                make_float4(p0.x, p0.y, p1.x, p1.y);
            *(float4*)(g_yr + pl + (size_t)(row0 + rA + 2) * 256 + col0 + cA) =
                make_float4(p2.x, p2.y, p3.x, p3.y);
        }
    }

    // ---- tail chunk: outputs 320..339 (20 outs; warps with oo*8 >= 20 skip) ----
    __syncthreads();
    #pragma unroll
    for (int k = 0; k < 16; k++) {
        int i = t + k * 256;
        int c = i >> 6, o = i & 63;
        Wk[i] = (o < 20) ? Win[(320 + o) * 64 + c] : 0.0f;
    }
    __syncthreads();

    if (oo * 8 < 20) {   // warp-uniform: only warps 0..2 do the tail
        ull acc[8][4];
        #pragma unroll
        for (int o = 0; o < 8; o++)
            #pragma unroll
            for (int j = 0; j < 4; j++) acc[o][j] = 0ull;

        #pragma unroll 4
        for (int c = 0; c < 64; c++) {
            float4 xa  = *(const float4*)(xs + c * 256 + po * 4);
            float4 xb4 = *(const float4*)(xs + c * 256 + po * 4 + 128);
            ull x0 = pk(xa.x, xa.y),   x1 = pk(xa.z, xa.w);
            ull x2 = pk(xb4.x, xb4.y), x3 = pk(xb4.z, xb4.w);
            float4 wa = *(const float4*)(Wk + c * 64 + oo * 8);
            float4 wb = *(const float4*)(Wk + c * 64 + oo * 8 + 4);
            float wv[8] = {wa.x, wa.y, wa.z, wa.w, wb.x, wb.y, wb.z, wb.w};
            #pragma unroll
            for (int o = 0; o < 8; o++) {
                ull wd = pk(wv[o], wv[o]);
                fma2(acc[o][0], wd, x0);
                fma2(acc[o][1], wd, x1);
                fma2(acc[o][2], wd, x2);
                fma2(acc[o][3], wd, x3);
            }
        }

        #pragma unroll
        for (int o = 0; o < 8; o++) {
            int og = 320 + oo * 8 + o;
            if (og < 340) {
                float2 p0 = upk(acc[o][0]), p1 = upk(acc[o][1]);
                float2 p2 = upk(acc[o][2]), p3 = upk(acc[o][3]);
                size_t pl = ((size_t)b * 340 + og) * 65536;
                *(float4*)(g_yr + pl + (size_t)(row0 + rA) * 256 + col0 + cA) =
                    make_float4(p0.x, p0.y, p1.x, p1.y);
                *(float4*)(g_yr + pl + (size_t)(row0 + rA + 2) * 256 + col0 + cA) =
                    make_float4(p2.x, p2.y, p3.x, p3.y);
            }
        }
    }
}

// ---------------------------------------------------------------------------
// Fallback kernel A (quant != ones): fused proj_in + DCT + quant + IDCT.
// ---------------------------------------------------------------------------
__global__ void __launch_bounds__(256, 2) kernA(
    const float* __restrict__ x, const float* __restrict__ Win,
    const float* __restrict__ quant)
{
    if (*(volatile int*)&g_ones) return;

    extern __shared__ float sm[];
    float* xs   = sm;
    float* bufA = sm + 16384;
    float* bufB = sm + 18688;
    float* Wk   = sm + 20992;
    float* qk   = sm + 21504;
    float* Ms   = sm + 22016;

    const int t  = threadIdx.x;
    const int b  = blockIdx.z;
    const int tx = blockIdx.x, ty = blockIdx.y;
    const int lx = t & 15, ly = t >> 4;
    const int gx = tx * 16 + lx, gy = ty * 16 + ly;

    if (t < 64) {
        int i = t >> 3, j = t & 7;
        Ms[t] = (i == 0) ? 0.3535533905932738f
                         : 0.5f * cosf((float)M_PI * (float)(i * (2 * j + 1)) / 16.0f);
    }
    {
        const float* xb = x + ((size_t)b << 22);
        int pofs = gy * 256 + gx;
        #pragma unroll
        for (int c = 0; c < 64; c++)
            xs[c * 256 + t] = xb[c * 65536 + pofs];
    }

    const int ch  = t >> 5;
    const int pat = (t >> 3) & 3;
    const int ln  = t & 7;
    float* pA = bufA + ch * 288 + pat * 72;
    float* pB = bufB + ch * 288 + pat * 72;

    const int patc = ((ly >> 3) << 1) + (lx >> 3);
    const int rr = ly & 7, cc = lx & 7;
    float* convDst = bufA + patc * 72 + rr * 9 + cc;

    for (int o0 = 0; o0 < 340; o0 += 8) {
        #pragma unroll
        for (int r = 0; r < 2; r++) {
            int idx = t + r * 256;
            int c = idx >> 3, o = idx & 7;
            Wk[idx] = (o0 + o < 340) ? Win[(o0 + o) * 64 + c] : 0.0f;
            int o2 = idx >> 6, rc = idx & 63;
            qk[idx] = (o0 + o2 < 340) ? quant[(o0 + o2) * 64 + rc] : 0.0f;
        }
        __syncthreads();

        float acc[8] = {0.f, 0.f, 0.f, 0.f, 0.f, 0.f, 0.f, 0.f};
        #pragma unroll 8
        for (int c = 0; c < 64; c++) {
            float  xv = xs[c * 256 + t];
            float4 w0 = *reinterpret_cast<const float4*>(Wk + c * 8);
            float4 w1 = *reinterpret_cast<const float4*>(Wk + c * 8 + 4);
            acc[0] += w0.x * xv; acc[1] += w0.y * xv;
            acc[2] += w0.z * xv; acc[3] += w0.w * xv;
            acc[4] += w1.x * xv; acc[5] += w1.y * xv;
            acc[6] += w1.z * xv; acc[7] += w1.w * xv;
        }
        #pragma unroll
        for (int o = 0; o < 8; o++) convDst[o * 288] = acc[o];
        __syncthreads();

        float v[8];
        #pragma unroll
        for (int p = 0; p < 8; p++) v[p] = pA[p * 9 + ln];
        #pragma unroll
        for (int i = 0; i < 8; i++) {
            float s = 0.f;
            #pragma unroll
            for (int p = 0; p < 8; p++) s += Ms[i * 8 + p] * v[p];
            pB[i * 9 + ln] = s;
        }
        __syncthreads();

        #pragma unroll
        for (int q = 0; q < 8; q++) v[q] = pB[ln * 9 + q];
        #pragma unroll
        for (int j = 0; j < 8; j++) {
            float s = 0.f;
            #pragma unroll
            for (int q = 0; q < 8; q++) s += v[q] * Ms[j * 8 + q];
            pA[ln * 9 + j] = s * qk[ch * 64 + ln * 8 + j];
        }
        __syncthreads();

        #pragma unroll
        for (int p = 0; p < 8; p++) v[p] = pA[p * 9 + ln];
        #pragma unroll
        for (int i = 0; i < 8; i++) {
            float s = 0.f;
            #pragma unroll
            for (int p = 0; p < 8; p++) s += Ms[p * 8 + i] * v[p];
            pB[i * 9 + ln] = s;
        }
        __syncthreads();

        #pragma unroll
        for (int q = 0; q < 8; q++) v[q] = pB[ln * 9 + q];
        int o = o0 + ch;
        if (o < 340) {
            float r8[8];
            #pragma unroll
            for (int j = 0; j < 8; j++) {
                float s = 0.f;
                #pragma unroll
                for (int q = 0; q < 8; q++) s += v[q] * Ms[q * 8 + j];
                r8[j] = s;
            }
            int py = pat >> 1, px = pat & 1;
            size_t base = (((size_t)b * 340 + o) * 256 +
                           (size_t)(ty * 16 + py * 8 + ln)) * 256 +
                          (size_t)(tx * 16 + px * 8);
            float4* dst = reinterpret_cast<float4*>(g_yr + base);
            dst[0] = make_float4(r8[0], r8[1], r8[2], r8[3]);
            dst[1] = make_float4(r8[4], r8[5], r8[6], r8[7]);
        }
    }
}

// ---------------------------------------------------------------------------
// Kernel B4: fused depthwise 3x3 + exact-GELU gate + proj_out.
// 3-stage cp.async pipeline, 4 channel-pairs per barrier round (43 rounds;
// last round carries 2 valid pairs). Dyn smem:
//   Wo 43520 | pdw 12240 | tb 3 stages x 4 pairs x 324 f2 = 31104 -> 86864 B.
// ---------------------------------------------------------------------------
__global__ void __launch_bounds__(256, 2) kernB4(
    const float* __restrict__ Wdw, const float* __restrict__ Wout,
    float* __restrict__ out)
{
    extern __shared__ float smB[];
    float*  Wo  = smB;                      // [oh][64]
    float2* pdw = (float2*)(smB + 10880);   // [oh][9]  packed {w1,w2}
    float2* tb  = (float2*)(smB + 13940);   // [3][4][324]

    const int t  = threadIdx.x;
    const int b  = blockIdx.z;
    const int tx = blockIdx.x, ty = blockIdx.y;
    const int lx = t & 15, ly = t >> 4;
    const int gx = tx * 16 + lx, gy = ty * 16 + ly;

    for (int i = t; i < 10880; i += 256)
        Wo[i] = Wout[(i & 63) * 170 + (i >> 6)];
    for (int i = t; i < 1530; i += 256) {
        int oh = i / 9, k = i - oh * 9;
        pdw[i] = make_float2(Wdw[oh * 9 + k], Wdw[(oh + 170) * 9 + k]);
    }

    // Halo slots: slot1 = t (always < 324), slot2 = t + 256 (valid t < 68).
    const size_t bbase = (size_t)b * 340 * 65536;
    int r1i = t / 18, c1i = t - r1i * 18;
    int yy1 = ty * 16 + r1i - 1, xx1 = tx * 16 + c1i - 1;
    bool in1 = ((unsigned)yy1 < 256u) && ((unsigned)xx1 < 256u);
    size_t e1 = in1 ? bbase + (size_t)yy1 * 256 + xx1 : bbase;
    const unsigned sz1 = in1 ? 4u : 0u;

    const int i2 = t + 256;
    int r2i = i2 / 18, c2i = i2 - r2i * 18;
    int yy2 = ty * 16 + r2i - 1, xx2 = tx * 16 + c2i - 1;
    const bool hv2 = (t < 68);
    bool in2 = hv2 && ((unsigned)yy2 < 256u) && ((unsigned)xx2 < 256u);
    size_t e2 = in2 ? bbase + (size_t)yy2 * 256 + xx2 : bbase;
    const unsigned sz2 = in2 ? 4u : 0u;

    const uint64_t yrg = gmem_u64(g_yr);
    const uint64_t g1 = yrg + e1 * 4;
    const uint64_t g2 = yrg + e2 * 4;
    const uint32_t tbu32 = smem_u32(tb);
    const uint64_t CH  = 262144ull;           // one channel plane, bytes
    const uint64_t CHB = 170ull * 262144ull;  // gate-half offset, bytes

    // Round r loads pairs 4r..4r+3 into stage r%3 (zero-fill past oh 169).
    auto load_round = [&](int r) {
        uint32_t sb = tbu32 + (uint32_t)(r % 3) * 10368u;
        #pragma unroll
        for (int p = 0; p < 4; p++) {
            int oh = 4 * r + p;
            unsigned ok = (oh < 170) ? 1u : 0u;
            uint64_t off = (uint64_t)(ok ? oh : 0) * CH;
            uint32_t sp = sb + (uint32_t)p * 2592u;
            cp4(sp + t * 8u,      g1 + off,       sz1 * ok);
            cp4(sp + t * 8u + 4u, g1 + off + CHB, sz1 * ok);
            if (hv2) {
                cp4(sp + i2 * 8u,      g2 + off,       sz2 * ok);
                cp4(sp + i2 * 8u + 4u, g2 + off + CHB, sz2 * ok);
            }
        }
    };

    load_round(0); cp_commit();
    load_round(1); cp_commit();

    ull acc[32];
    #pragma unroll
    for (int j = 0; j < 32; j++) acc[j] = 0ull;

    const ull*        pdwu = (const ull*)pdw;
    const ulonglong2* Wo2  = (const ulonglong2*)Wo;

    for (int r = 0; r < 43; r++) {
        cp_wait1();
        __syncthreads();

        if (r + 2 < 43) load_round(r + 2);
        cp_commit();

        const ull* tbs = (const ull*)((const char*)tb + (size_t)(r % 3) * 10368);
        #pragma unroll
        for (int pr = 0; pr < 4; pr++) {
            int oh = 4 * r + pr;
            if (oh < 170) {
                ull d2 = 0ull;
                #pragma unroll
                for (int ky = 0; ky < 3; ky++)
                    #pragma unroll
                    for (int kx = 0; kx < 3; kx++)
                        fma2(d2, tbs[pr * 324 + (ly + ky) * 18 + lx + kx],
                                 pdwu[oh * 9 + ky * 3 + kx]);
                float2 d = upk(d2);
                float g = 0.5f * d.x * (1.0f + erff(d.x * 0.7071067811865476f)) * d.y;
                ull gg = pk(g, g);
                #pragma unroll
                for (int j4 = 0; j4 < 16; j4++) {
                    ulonglong2 w2 = Wo2[oh * 16 + j4];
                    fma2(acc[j4 * 2 + 0], gg, w2.x);
                    fma2(acc[j4 * 2 + 1], gg, w2.y);
                }
            }
        }
    }

    size_t obase = ((size_t)b * 64) * 65536 + (size_t)gy * 256 + (size_t)gx;
    #pragma unroll
    for (int j = 0; j < 32; j++) {
        float2 v = upk(acc[j]);
        out[obase + (size_t)(j * 2 + 0) * 65536] = v.x;
        out[obase + (size_t)(j * 2 + 1) * 65536] = v.y;
    }
}

// ---------------------------------------------------------------------------
extern "C" void kernel_launch(void* const* d_in, const int* in_sizes, int n_in,
                              void* d_out, int out_size)
{
    (void)in_sizes; (void)n_in; (void)out_size;
    const float* x     = (const float*)d_in[0];  // [4,64,256,256]
    const float* Win   = (const float*)d_in[1];  // [340,64]
    const float* Wdw   = (const float*)d_in[2];  // [340,1,3,3]
    const float* quant = (const float*)d_in[3];  // [340,1,1,8,8]
    const float* Wout  = (const float*)d_in[4];  // [64,170]
    float* out = (float*)d_out;                  // [4,64,256,256]

    static int attr_done = 0;
    if (!attr_done) {
        cudaFuncSetAttribute(kernA,  cudaFuncAttributeMaxDynamicSharedMemorySize, 88320);
        cudaFuncSetAttribute(kernA2, cudaFuncAttributeMaxDynamicSharedMemorySize, 81920);
        cudaFuncSetAttribute(kernB4, cudaFuncAttributeMaxDynamicSharedMemorySize, 86864);
        attr_done = 1;
    }

    kinit<<<1, 32>>>();
    kcheck<<<85, 256>>>(quant);

    dim3 gOld(16, 16, 4), blk(256);
    kernA<<<gOld, blk, 88320>>>(x, Win, quant);   // runs only if quant != 1

    dim3 gA2(4, 64, 4);
    kernA2<<<gA2, blk, 81920>>>(x, Win);          // runs only if quant == 1

    kernB4<<<gOld, blk, 86864>>>(Wdw, Wout, out);
}

// round 9
// speedup vs baseline: 1.1715x; 1.1715x over previous
#include <cuda_runtime.h>
#include <math.h>
#include <stdint.h>

#ifndef M_PI
#define M_PI 3.14159265358979323846
#endif

// Intermediate yr, shape [4][340][256][256] fp32 (~357 MB), device global.
__device__ float g_yr[89128960];
// 1 if quant is all-ones (DCT->quant->IDCT is identity), else 0.
__device__ int g_ones;

typedef unsigned long long ull;

// ---- packed f32x2 helpers ----
__device__ __forceinline__ ull pk(float x, float y) {
    ull r;
    asm("mov.b64 %0, {%1, %2};" : "=l"(r) : "r"(__float_as_int(x)), "r"(__float_as_int(y)));
    return r;
}
__device__ __forceinline__ void fma2(ull& d, ull a, ull b) {
    asm("fma.rn.f32x2 %0, %1, %2, %0;" : "+l"(d) : "l"(a), "l"(b));
}
__device__ __forceinline__ float2 upk(ull v) {
    int lo, hi;
    asm("mov.b64 {%0, %1}, %2;" : "=r"(lo), "=r"(hi) : "l"(v));
    return make_float2(__int_as_float(lo), __int_as_float(hi));
}

// ---- cp.async helpers ----
__device__ __forceinline__ void cp4(uint32_t dst, uint64_t gsrc, unsigned sz) {
    asm volatile("cp.async.ca.shared.global [%0], [%1], 4, %2;"
                 :: "r"(dst), "l"(gsrc), "r"(sz));
}
__device__ __forceinline__ void cp_commit() {
    asm volatile("cp.async.commit_group;" ::: "memory");
}
__device__ __forceinline__ void cp_wait2() {
    asm volatile("cp.async.wait_group 2;" ::: "memory");
}
__device__ __forceinline__ uint32_t smem_u32(const void* p) {
    uint32_t a;
    asm("{ .reg .u64 t; cvta.to.shared.u64 t, %1; cvt.u32.u64 %0, t; }"
        : "=r"(a) : "l"(p));
    return a;
}
__device__ __forceinline__ uint64_t gmem_u64(const void* p) {
    uint64_t a;
    asm("cvta.to.global.u64 %0, %1;" : "=l"(a) : "l"(p));
    return a;
}

// ---------------------------------------------------------------------------
// Flag kernels: detect quant == all-ones.
// ---------------------------------------------------------------------------
__global__ void kinit() {
    if (threadIdx.x == 0) g_ones = 1;
}
__global__ void kcheck(const float* __restrict__ quant) {
    int i = blockIdx.x * 256 + threadIdx.x;   // 85*256 == 21760
    if (quant[i] != 1.0f) atomicExch(&g_ones, 0);
}

// ---------------------------------------------------------------------------
// Fast path kernel A2 (quant == ones): proj_in register-blocked f32x2 GEMM.
// (Unchanged from R8: measured 290 us.)
// ---------------------------------------------------------------------------
__global__ void __launch_bounds__(256, 2) kernA2(
    const float* __restrict__ x, const float* __restrict__ Win)
{
    if (!*(volatile int*)&g_ones) return;

    extern __shared__ float sm[];
    float* xs = sm;            // [c][p]
    float* Wk = sm + 16384;    // [c][o] transposed chunk

    const int t = threadIdx.x;
    const int b = blockIdx.z;
    const int row0 = blockIdx.y * 4;
    const int col0 = blockIdx.x * 64;

    {
        const float* xb = x + ((size_t)b << 22);
        #pragma unroll
        for (int k = 0; k < 16; k++) {
            int i = t + k * 256;
            int c = i >> 6, q = i & 63;
            int r = q >> 4, cc = (q & 15) * 4;
            float4 v = *(const float4*)(xb + ((size_t)c * 256 + row0 + r) * 256 + col0 + cc);
            *(float4*)(xs + c * 256 + q * 4) = v;
        }
    }

    const int po = t & 31;
    const int oo = t >> 5;
    const int rA = po >> 4, cA = (po * 4) & 63;

    for (int o0 = 0; o0 < 320; o0 += 64) {
        __syncthreads();
        #pragma unroll
        for (int k = 0; k < 16; k++) {
            int i = t + k * 256;
            int c = i >> 6, o = i & 63;
            Wk[i] = Win[(o0 + o) * 64 + c];
        }
        __syncthreads();

        ull acc[8][4];
        #pragma unroll
        for (int o = 0; o < 8; o++)
            #pragma unroll
            for (int j = 0; j < 4; j++) acc[o][j] = 0ull;

        #pragma unroll 4
        for (int c = 0; c < 64; c++) {
            float4 xa  = *(const float4*)(xs + c * 256 + po * 4);
            float4 xb4 = *(const float4*)(xs + c * 256 + po * 4 + 128);
            ull x0 = pk(xa.x, xa.y),   x1 = pk(xa.z, xa.w);
            ull x2 = pk(xb4.x, xb4.y), x3 = pk(xb4.z, xb4.w);
            float4 wa = *(const float4*)(Wk + c * 64 + oo * 8);
            float4 wb = *(const float4*)(Wk + c * 64 + oo * 8 + 4);
            float wv[8] = {wa.x, wa.y, wa.z, wa.w, wb.x, wb.y, wb.z, wb.w};
            #pragma unroll
            for (int o = 0; o < 8; o++) {
                ull wd = pk(wv[o], wv[o]);
                fma2(acc[o][0], wd, x0);
                fma2(acc[o][1], wd, x1);
                fma2(acc[o][2], wd, x2);
                fma2(acc[o][3], wd, x3);
            }
        }

        #pragma unroll
        for (int o = 0; o < 8; o++) {
            int og = o0 + oo * 8 + o;
            float2 p0 = upk(acc[o][0]), p1 = upk(acc[o][1]);
            float2 p2 = upk(acc[o][2]), p3 = upk(acc[o][3]);
            size_t pl = ((size_t)b * 340 + og) * 65536;
            *(float4*)(g_yr + pl + (size_t)(row0 + rA) * 256 + col0 + cA) =
                make_float4(p0.x, p0.y, p1.x, p1.y);
            *(float4*)(g_yr + pl + (size_t)(row0 + rA + 2) * 256 + col0 + cA) =
                make_float4(p2.x, p2.y, p3.x, p3.y);
        }
    }

    // tail chunk: outputs 320..339
    __syncthreads();
    #pragma unroll
    for (int k = 0; k < 16; k++) {
        int i = t + k * 256;
        int c = i >> 6, o = i & 63;
        Wk[i] = (o < 20) ? Win[(320 + o) * 64 + c] : 0.0f;
    }
    __syncthreads();

    if (oo * 8 < 20) {
        ull acc[8][4];
        #pragma unroll
        for (int o = 0; o < 8; o++)
            #pragma unroll
            for (int j = 0; j < 4; j++) acc[o][j] = 0ull;

        #pragma unroll 4
        for (int c = 0; c < 64; c++) {
            float4 xa  = *(const float4*)(xs + c * 256 + po * 4);
            float4 xb4 = *(const float4*)(xs + c * 256 + po * 4 + 128);
            ull x0 = pk(xa.x, xa.y),   x1 = pk(xa.z, xa.w);
            ull x2 = pk(xb4.x, xb4.y), x3 = pk(xb4.z, xb4.w);
            float4 wa = *(const float4*)(Wk + c * 64 + oo * 8);
            float4 wb = *(const float4*)(Wk + c * 64 + oo * 8 + 4);
            float wv[8] = {wa.x, wa.y, wa.z, wa.w, wb.x, wb.y, wb.z, wb.w};
            #pragma unroll
            for (int o = 0; o < 8; o++) {
                ull wd = pk(wv[o], wv[o]);
                fma2(acc[o][0], wd, x0);
                fma2(acc[o][1], wd, x1);
                fma2(acc[o][2], wd, x2);
                fma2(acc[o][3], wd, x3);
            }
        }

        #pragma unroll
        for (int o = 0; o < 8; o++) {
            int og = 320 + oo * 8 + o;
            if (og < 340) {
                float2 p0 = upk(acc[o][0]), p1 = upk(acc[o][1]);
                float2 p2 = upk(acc[o][2]), p3 = upk(acc[o][3]);
                size_t pl = ((size_t)b * 340 + og) * 65536;
                *(float4*)(g_yr + pl + (size_t)(row0 + rA) * 256 + col0 + cA) =
                    make_float4(p0.x, p0.y, p1.x, p1.y);
                *(float4*)(g_yr + pl + (size_t)(row0 + rA + 2) * 256 + col0 + cA) =
                    make_float4(p2.x, p2.y, p3.x, p3.y);
            }
        }
    }
}

// ---------------------------------------------------------------------------
// Fallback kernel A (quant != ones): fused proj_in + DCT + quant + IDCT.
// ---------------------------------------------------------------------------
__global__ void __launch_bounds__(256, 2) kernA(
    const float* __restrict__ x, const float* __restrict__ Win,
    const float* __restrict__ quant)
{
    if (*(volatile int*)&g_ones) return;

    extern __shared__ float sm[];
    float* xs   = sm;
    float* bufA = sm + 16384;
    float* bufB = sm + 18688;
    float* Wk   = sm + 20992;
    float* qk   = sm + 21504;
    float* Ms   = sm + 22016;

    const int t  = threadIdx.x;
    const int b  = blockIdx.z;
    const int tx = blockIdx.x, ty = blockIdx.y;
    const int lx = t & 15, ly = t >> 4;
    const int gx = tx * 16 + lx, gy = ty * 16 + ly;

    if (t < 64) {
        int i = t >> 3, j = t & 7;
        Ms[t] = (i == 0) ? 0.3535533905932738f
                         : 0.5f * cosf((float)M_PI * (float)(i * (2 * j + 1)) / 16.0f);
    }
    {
        const float* xb = x + ((size_t)b << 22);
        int pofs = gy * 256 + gx;
        #pragma unroll
        for (int c = 0; c < 64; c++)
            xs[c * 256 + t] = xb[c * 65536 + pofs];
    }

    const int ch  = t >> 5;
    const int pat = (t >> 3) & 3;
    const int ln  = t & 7;
    float* pA = bufA + ch * 288 + pat * 72;
    float* pB = bufB + ch * 288 + pat * 72;

    const int patc = ((ly >> 3) << 1) + (lx >> 3);
    const int rr = ly & 7, cc = lx & 7;
    float* convDst = bufA + patc * 72 + rr * 9 + cc;

    for (int o0 = 0; o0 < 340; o0 += 8) {
        #pragma unroll
        for (int r = 0; r < 2; r++) {
            int idx = t + r * 256;
            int c = idx >> 3, o = idx & 7;
            Wk[idx] = (o0 + o < 340) ? Win[(o0 + o) * 64 + c] : 0.0f;
            int o2 = idx >> 6, rc = idx & 63;
            qk[idx] = (o0 + o2 < 340) ? quant[(o0 + o2) * 64 + rc] : 0.0f;
        }
        __syncthreads();

        float acc[8] = {0.f, 0.f, 0.f, 0.f, 0.f, 0.f, 0.f, 0.f};
        #pragma unroll 8
        for (int c = 0; c < 64; c++) {
            float  xv = xs[c * 256 + t];
            float4 w0 = *reinterpret_cast<const float4*>(Wk + c * 8);
            float4 w1 = *reinterpret_cast<const float4*>(Wk + c * 8 + 4);
            acc[0] += w0.x * xv; acc[1] += w0.y * xv;
            acc[2] += w0.z * xv; acc[3] += w0.w * xv;
            acc[4] += w1.x * xv; acc[5] += w1.y * xv;
            acc[6] += w1.z * xv; acc[7] += w1.w * xv;
        }
        #pragma unroll
        for (int o = 0; o < 8; o++) convDst[o * 288] = acc[o];
        __syncthreads();

        float v[8];
        #pragma unroll
        for (int p = 0; p < 8; p++) v[p] = pA[p * 9 + ln];
        #pragma unroll
        for (int i = 0; i < 8; i++) {
            float s = 0.f;
            #pragma unroll
            for (int p = 0; p < 8; p++) s += Ms[i * 8 + p] * v[p];
            pB[i * 9 + ln] = s;
        }
        __syncthreads();

        #pragma unroll
        for (int q = 0; q < 8; q++) v[q] = pB[ln * 9 + q];
        #pragma unroll
        for (int j = 0; j < 8; j++) {
            float s = 0.f;
            #pragma unroll
            for (int q = 0; q < 8; q++) s += v[q] * Ms[j * 8 + q];
            pA[ln * 9 + j] = s * qk[ch * 64 + ln * 8 + j];
        }
        __syncthreads();

        #pragma unroll
        for (int p = 0; p < 8; p++) v[p] = pA[p * 9 + ln];
        #pragma unroll
        for (int i = 0; i < 8; i++) {
            float s = 0.f;
            #pragma unroll
            for (int p = 0; p < 8; p++) s += Ms[p * 8 + i] * v[p];
            pB[i * 9 + ln] = s;
        }
        __syncthreads();

        #pragma unroll
        for (int q = 0; q < 8; q++) v[q] = pB[ln * 9 + q];
        int o = o0 + ch;
        if (o < 340) {
            float r8[8];
            #pragma unroll
            for (int j = 0; j < 8; j++) {
                float s = 0.f;
                #pragma unroll
                for (int q = 0; q < 8; q++) s += v[q] * Ms[q * 8 + j];
                r8[j] = s;
            }
            int py = pat >> 1, px = pat & 1;
            size_t base = (((size_t)b * 340 + o) * 256 +
                           (size_t)(ty * 16 + py * 8 + ln)) * 256 +
                          (size_t)(tx * 16 + px * 8);
            float4* dst = reinterpret_cast<float4*>(g_yr + base);
            dst[0] = make_float4(r8[0], r8[1], r8[2], r8[3]);
            dst[1] = make_float4(r8[4], r8[5], r8[6], r8[7]);
        }
    }
}

// ---------------------------------------------------------------------------
// Kernel B5: fused depthwise 3x3 + exact-GELU gate + proj_out.
// B3 structure (2 channel-pairs per round, 85 rounds) with a DEEPER pipeline:
// 4 cp.async stages, wait_group 2 (3 rounds of prefetch in flight).
// Dyn smem: Wo 43520 | pdw 12240 | tb 4 stages x 2 pairs x 324 f2 = 20736
//   -> 76496 B total. occ 2.
// ---------------------------------------------------------------------------
__global__ void __launch_bounds__(256, 2) kernB5(
    const float* __restrict__ Wdw, const float* __restrict__ Wout,
    float* __restrict__ out)
{
    extern __shared__ float smB[];
    float*  Wo  = smB;                      // [oh][64]
    float2* pdw = (float2*)(smB + 10880);   // [oh][9]  packed {w1,w2}
    float2* tb  = (float2*)(smB + 13940);   // [4][2][324]

    const int t  = threadIdx.x;
    const int b  = blockIdx.z;
    const int tx = blockIdx.x, ty = blockIdx.y;
    const int lx = t & 15, ly = t >> 4;
    const int gx = tx * 16 + lx, gy = ty * 16 + ly;

    for (int i = t; i < 10880; i += 256)
        Wo[i] = Wout[(i & 63) * 170 + (i >> 6)];
    for (int i = t; i < 1530; i += 256) {
        int oh = i / 9, k = i - oh * 9;
        pdw[i] = make_float2(Wdw[oh * 9 + k], Wdw[(oh + 170) * 9 + k]);
    }

    // Halo slots: slot1 = t (always < 324), slot2 = t + 256 (valid t < 68).
    const size_t bbase = (size_t)b * 340 * 65536;
    int r1i = t / 18, c1i = t - r1i * 18;
    int yy1 = ty * 16 + r1i - 1, xx1 = tx * 16 + c1i - 1;
    bool in1 = ((unsigned)yy1 < 256u) && ((unsigned)xx1 < 256u);
    size_t e1 = in1 ? bbase + (size_t)yy1 * 256 + xx1 : bbase;
    const unsigned sz1 = in1 ? 4u : 0u;

    const int i2 = t + 256;
    int r2i = i2 / 18, c2i = i2 - r2i * 18;
    int yy2 = ty * 16 + r2i - 1, xx2 = tx * 16 + c2i - 1;
    const bool hv2 = (t < 68);
    bool in2 = hv2 && ((unsigned)yy2 < 256u) && ((unsigned)xx2 < 256u);
    size_t e2 = in2 ? bbase + (size_t)yy2 * 256 + xx2 : bbase;
    const unsigned sz2 = in2 ? 4u : 0u;

    const uint64_t yrg = gmem_u64(g_yr);
    const uint64_t g1 = yrg + e1 * 4;
    const uint64_t g2 = yrg + e2 * 4;
    const uint32_t tbu32 = smem_u32(tb);
    const uint64_t CH  = 262144ull;           // one channel plane, bytes
    const uint64_t CHB = 170ull * 262144ull;  // gate-half offset, bytes

    // Round r loads pairs (2r, 2r+1) into stage r%4.
    auto load_round = [&](int r) {
        uint32_t sb = tbu32 + (uint32_t)(r & 3) * 5184u;
        uint64_t s1 = g1 + (uint64_t)(2 * r) * CH;
        cp4(sb + t * 8u,      s1,       sz1);
        cp4(sb + t * 8u + 4u, s1 + CHB, sz1);
        cp4(sb + 2592u + t * 8u,      s1 + CH,       sz1);
        cp4(sb + 2592u + t * 8u + 4u, s1 + CH + CHB, sz1);
        if (hv2) {
            uint64_t s2 = g2 + (uint64_t)(2 * r) * CH;
            cp4(sb + i2 * 8u,      s2,       sz2);
            cp4(sb + i2 * 8u + 4u, s2 + CHB, sz2);
            cp4(sb + 2592u + i2 * 8u,      s2 + CH,       sz2);
            cp4(sb + 2592u + i2 * 8u + 4u, s2 + CH + CHB, sz2);
        }
    };

    // Prologue: rounds 0..2 in flight.
    load_round(0); cp_commit();
    load_round(1); cp_commit();
    load_round(2); cp_commit();

    ull acc[32];
    #pragma unroll
    for (int j = 0; j < 32; j++) acc[j] = 0ull;

    const ull*        pdwu = (const ull*)pdw;
    const ulonglong2* Wo2  = (const ulonglong2*)Wo;

    for (int r = 0; r < 85; r++) {
        cp_wait2();          // group r complete (2 newer groups may be in flight)
        __syncthreads();     // all threads see round-r data; stage (r+3)%4 free

        if (r + 3 < 85) load_round(r + 3);
        cp_commit();         // always commit (keeps group accounting uniform)

        const ull* tbs = (const ull*)((const char*)tb + (size_t)(r & 3) * 5184);
        #pragma unroll
        for (int pr = 0; pr < 2; pr++) {
            int oh = 2 * r + pr;
            ull d2 = 0ull;
            #pragma unroll
            for (int ky = 0; ky < 3; ky++)
                #pragma unroll
                for (int kx = 0; kx < 3; kx++)
                    fma2(d2, tbs[pr * 324 + (ly + ky) * 18 + lx + kx],
                             pdwu[oh * 9 + ky * 3 + kx]);
            float2 d = upk(d2);
            float g = 0.5f * d.x * (1.0f + erff(d.x * 0.7071067811865476f)) * d.y;
            ull gg = pk(g, g);
            #pragma unroll
            for (int j4 = 0; j4 < 16; j4++) {
                ulonglong2 w2 = Wo2[oh * 16 + j4];
                fma2(acc[j4 * 2 + 0], gg, w2.x);
                fma2(acc[j4 * 2 + 1], gg, w2.y);
            }
        }
    }

    size_t obase = ((size_t)b * 64) * 65536 + (size_t)gy * 256 + (size_t)gx;
    #pragma unroll
    for (int j = 0; j < 32; j++) {
        float2 v = upk(acc[j]);
        out[obase + (size_t)(j * 2 + 0) * 65536] = v.x;
        out[obase + (size_t)(j * 2 + 1) * 65536] = v.y;
    }
}

// ---------------------------------------------------------------------------
extern "C" void kernel_launch(void* const* d_in, const int* in_sizes, int n_in,
                              void* d_out, int out_size)
{
    (void)in_sizes; (void)n_in; (void)out_size;
    const float* x     = (const float*)d_in[0];  // [4,64,256,256]
    const float* Win   = (const float*)d_in[1];  // [340,64]
    const float* Wdw   = (const float*)d_in[2];  // [340,1,3,3]
    const float* quant = (const float*)d_in[3];  // [340,1,1,8,8]
    const float* Wout  = (const float*)d_in[4];  // [64,170]
    float* out = (float*)d_out;                  // [4,64,256,256]

    static int attr_done = 0;
    if (!attr_done) {
        cudaFuncSetAttribute(kernA,  cudaFuncAttributeMaxDynamicSharedMemorySize, 88320);
        cudaFuncSetAttribute(kernA2, cudaFuncAttributeMaxDynamicSharedMemorySize, 81920);
        cudaFuncSetAttribute(kernB5, cudaFuncAttributeMaxDynamicSharedMemorySize, 76496);
        attr_done = 1;
    }

    kinit<<<1, 32>>>();
    kcheck<<<85, 256>>>(quant);

    dim3 gOld(16, 16, 4), blk(256);
    kernA<<<gOld, blk, 88320>>>(x, Win, quant);   // runs only if quant != 1

    dim3 gA2(4, 64, 4);
    kernA2<<<gA2, blk, 81920>>>(x, Win);          // runs only if quant == 1

    kernB5<<<gOld, blk, 76496>>>(Wdw, Wout, out);
}